// round 2
// baseline (speedup 1.0000x reference)
#include <cuda_runtime.h>
#include <cstdint>

#define B_ 8
#define I_ 16
#define H_ 32
#define W_ 32
#define C_ 64
#define F_ 128

typedef unsigned long long u64;

// Duplicate a float into both lanes of a packed f32x2 register.
__device__ __forceinline__ u64 pack_dup(float v) {
    u64 r;
    unsigned int b = __float_as_uint(v);
    asm("mov.b64 %0, {%1, %1};" : "=l"(r) : "r"(b));
    return r;
}

// Packed dual-FMA: d = a * b + d (two fp32 lanes per instruction).
__device__ __forceinline__ void fma2(u64& d, u64 a, u64 b) {
    asm("fma.rn.f32x2 %0, %1, %2, %0;" : "+l"(d) : "l"(a), "l"(b));
}

// Tile: 128 output positions (4 rows x 32 cols) x 128 filters per block.
// 256 threads, each computes an 8m x 8f register tile (32 f32x2 accumulators).
// K loop: 9 kernel positions x 64 channels.
__global__ void __launch_bounds__(256, 2)
conv_kernel(const float* __restrict__ x, const float* __restrict__ kern,
            float* __restrict__ out)
{
    extern __shared__ float sm[];
    float* As = sm;              // [128 m][64 c]  (32 KB)
    float* Bs = sm + 128 * 64;   // [64 c][128 f]  (32 KB)

    const int tid = threadIdx.x;
    const int tx  = tid & 15;    // -> f group
    const int ty  = tid >> 4;    // -> m group
    const int f0  = tx * 8;
    const int m0  = ty * 8;

    const int oh0 = blockIdx.x * 4;   // 8 row-groups
    const int img = blockIdx.y;       // 16 images
    const int b   = blockIdx.z;       // 8 batches

    const float* xb = x + (size_t)(b * I_ + img) * (H_ * W_ * C_);
    const float* kb = kern + (size_t)b * (9 * C_ * F_);

    u64 acc[8][4];
    #pragma unroll
    for (int q = 0; q < 8; q++)
        #pragma unroll
        for (int j = 0; j < 4; j++) acc[q][j] = 0ull;

    #pragma unroll
    for (int kp = 0; kp < 9; ++kp) {
        const int kh = kp / 3 - 1;   // -1..1 row offset (compile-time)
        const int kw = kp % 3 - 1;   // -1..1 col offset (compile-time)

        __syncthreads();   // protect previous chunk's compute

        // --- Load A tile: im2col gather, 128 m x 64 c --------------------
        // idx -> (m = idx>>4, c4 = idx&15); consecutive threads cover
        // consecutive c4 => coalesced 256B reads per m-row; float4 smem
        // stores are conflict-free.
        #pragma unroll
        for (int it = 0; it < 8; ++it) {
            int idx = tid + it * 256;          // 0..2047
            int c4  = idx & 15;
            int m   = idx >> 4;
            int oh  = oh0 + (m >> 5);
            int ow  = m & 31;
            int ih  = oh + kh;
            int iw  = ow + kw;
            float4 v = make_float4(0.f, 0.f, 0.f, 0.f);
            if ((unsigned)ih < H_ && (unsigned)iw < W_)
                v = *(const float4*)(xb + ((ih * W_ + iw) * C_ + c4 * 4));
            *(float4*)(As + m * 64 + c4 * 4) = v;
        }

        // --- Load B tile: kernel[b][kh][kw][:][:] is a contiguous 32 KB --
        const float* kc = kb + kp * (C_ * F_);
        #pragma unroll
        for (int it = 0; it < 8; ++it) {
            int idx = tid + it * 256;          // 0..2047 float4s
            *(float4*)(Bs + idx * 4) = *(const float4*)(kc + idx * 4);
        }

        __syncthreads();

        // --- Compute: 64 channels, 8m x 8f per thread on f32x2 pipe ------
        #pragma unroll 4
        for (int c = 0; c < 64; ++c) {
            ulonglong2 b01 = *(const ulonglong2*)(Bs + c * 128 + f0);
            ulonglong2 b23 = *(const ulonglong2*)(Bs + c * 128 + f0 + 4);
            #pragma unroll
            for (int q = 0; q < 8; q++) {
                u64 a = pack_dup(As[(m0 + q) * 64 + c]);
                fma2(acc[q][0], a, b01.x);
                fma2(acc[q][1], a, b01.y);
                fma2(acc[q][2], a, b23.x);
                fma2(acc[q][3], a, b23.y);
            }
        }
    }

    // --- Epilogue: 8 f32 (2x16B) per m-row, f contiguous -----------------
    #pragma unroll
    for (int q = 0; q < 8; q++) {
        int m  = m0 + q;
        int oh = oh0 + (m >> 5);
        int ow = m & 31;
        float* op = out + ((size_t)((b * I_ + img) * H_ + oh) * W_ + ow) * F_ + f0;
        ulonglong2 v0; v0.x = acc[q][0]; v0.y = acc[q][1];
        ulonglong2 v1; v1.x = acc[q][2]; v1.y = acc[q][3];
        *(ulonglong2*)(op)     = v0;
        *(ulonglong2*)(op + 4) = v1;
    }
}

extern "C" void kernel_launch(void* const* d_in, const int* in_sizes, int n_in,
                              void* d_out, int out_size)
{
    const float* x = (const float*)d_in[0];   // (8,16,32,32,64) f32
    const float* k = (const float*)d_in[1];   // (8,3,3,64,128)  f32
    float* out = (float*)d_out;               // (8,16,32,32,128) f32

    const int smem = (128 * 64 + 64 * 128) * sizeof(float);  // 64 KB
    cudaFuncSetAttribute(conv_kernel,
                         cudaFuncAttributeMaxDynamicSharedMemorySize, smem);

    dim3 grid(8, 16, 8);   // (row-group, image, batch) = 1024 blocks
    conv_kernel<<<grid, 256, smem>>>(x, k, out);
}

// round 7
// speedup vs baseline: 2.4461x; 2.4461x over previous
#include <cuda_runtime.h>
#include <cuda_bf16.h>
#include <cstdint>

#define B_ 8
#define I_ 16
#define HH 32
#define WW 32
#define CC 64
#define FF 128

// Pre-converted / transposed weights: [(b*9+kp)][f][c], bf16 hi + lo halves.
__device__ __align__(128) __nv_bfloat16 g_khi[72 * FF * CC];
__device__ __align__(128) __nv_bfloat16 g_klo[72 * FF * CC];

// ---- smem layout (single stage, 64 KB) -------------------------------------
#define A_HI 0
#define A_LO 16384
#define B_HI 32768
#define B_LO 49152
#define SMEM_TOTAL 65536

// swizzle within a 128B row:  swz(r*128 + x) = r*128 + (x ^ ((r&7)<<4))
__device__ __forceinline__ uint32_t s2u(const void* p) {
    uint32_t a;
    asm("{ .reg .u64 t; cvta.to.shared.u64 t, %1; cvt.u32.u64 %0, t; }" : "=r"(a) : "l"(p));
    return a;
}
// pack bf16(hi_src)<<16 | bf16(lo_src)
__device__ __forceinline__ uint32_t bf2(float hi_src, float lo_src) {
    uint32_t r;
    asm("cvt.rn.bf16x2.f32 %0, %1, %2;" : "=r"(r) : "f"(hi_src), "f"(lo_src));
    return r;
}
__device__ __forceinline__ void ldsm4(uint32_t* r, uint32_t addr) {
    asm volatile("ldmatrix.sync.aligned.m8n8.x4.shared.b16 {%0,%1,%2,%3}, [%4];"
                 : "=r"(r[0]), "=r"(r[1]), "=r"(r[2]), "=r"(r[3]) : "r"(addr));
}
__device__ __forceinline__ void mma_bf16(float* d, const uint32_t* a, uint32_t b0, uint32_t b1) {
    asm volatile(
        "mma.sync.aligned.m16n8k16.row.col.f32.bf16.bf16.f32 "
        "{%0,%1,%2,%3}, {%4,%5,%6,%7}, {%8,%9}, {%0,%1,%2,%3};"
        : "+f"(d[0]), "+f"(d[1]), "+f"(d[2]), "+f"(d[3])
        : "r"(a[0]), "r"(a[1]), "r"(a[2]), "r"(a[3]), "r"(b0), "r"(b1));
}

// ------------------------------------------------ weight convert/transpose --
// kern[b][kh][kw][c][f] f32  ->  g_khi/g_klo[(b*9+kp)][f][c] bf16
__global__ void __launch_bounds__(256) wt_convert_kernel(const float* __restrict__ kern) {
    __shared__ unsigned short shi[FF * 66];   // pad 64->66 to kill bank conflicts
    __shared__ unsigned short slo[FF * 66];
    const int blk = blockIdx.x;               // b*9+kp, 72 blocks
    const float* in = kern + (size_t)blk * (CC * FF);

    for (int idx = threadIdx.x; idx < CC * FF; idx += 256) {
        int c = idx >> 7, f = idx & 127;      // in is [c][f], reads coalesced
        float v = in[idx];
        __nv_bfloat16 h = __float2bfloat16(v);
        float hf = __bfloat162float(h);
        __nv_bfloat16 l = __float2bfloat16(v - hf);
        shi[f * 66 + c] = __bfloat16_as_ushort(h);
        slo[f * 66 + c] = __bfloat16_as_ushort(l);
    }
    __syncthreads();
    unsigned short* oh = (unsigned short*)(g_khi + (size_t)blk * (FF * CC));
    unsigned short* ol = (unsigned short*)(g_klo + (size_t)blk * (FF * CC));
    for (int idx = threadIdx.x; idx < FF * CC; idx += 256) {
        int f = idx >> 6, c = idx & 63;
        oh[idx] = shi[f * 66 + c];
        ol[idx] = slo[f * 66 + c];
    }
}

// ---------------------------------------------------------- main MMA kernel -
// Tile: M=128 (4 oh rows x 32 ow) x N=128 filters, K = 9 kp x 64 c.
// bf16 hi/lo split, 3 mma passes per k-chunk (hi*hi, lo*hi, hi*lo).
// 8 warps: warp_m = wid&1 (2 x 64 M), warp_n = wid>>1 (4 x 32 N).
__global__ void __launch_bounds__(256, 2)
conv_mma_kernel(const float* __restrict__ x, float* __restrict__ out)
{
    extern __shared__ char smem[];
    const uint32_t sb = s2u(smem);
    const int tid  = threadIdx.x;
    const int lane = tid & 31;
    const int wid  = tid >> 5;
    const int warp_m = wid & 1;
    const int warp_n = wid >> 1;

    const int oh0 = blockIdx.x * 4;
    const int img = blockIdx.y;
    const int b   = blockIdx.z;
    const float* xb = x + (size_t)(b * I_ + img) * (HH * WW * CC);
    const char* kh_base = (const char*)(g_khi + (size_t)(b * 9) * (FF * CC));
    const char* kl_base = (const char*)(g_klo + (size_t)(b * 9) * (FF * CC));

    float acc[4][4][4];   // [mi][ni][reg]
    #pragma unroll
    for (int mi = 0; mi < 4; mi++)
        #pragma unroll
        for (int ni = 0; ni < 4; ni++)
            #pragma unroll
            for (int r = 0; r < 4; r++) acc[mi][ni][r] = 0.f;

    // per-lane ldmatrix address components
    const int a_m = lane & 15;                 // row within m16
    const int a_k = (lane >> 4) << 4;          // 0 / 16 byte (k half)
    const int b_n = (lane & 7) + ((lane >> 4) << 3);  // row within n16
    const int b_k = ((lane >> 3) & 1) << 4;    // 0 / 16 byte (k half)

    #pragma unroll 1
    for (int kp = 0; kp < 9; ++kp) {
        const int kh = kp / 3 - 1;
        const int kw = kp % 3 - 1;

        __syncthreads();   // previous iteration's compute done

        // -- A tile: gather x, split to bf16 hi/lo, store swizzled ----------
        #pragma unroll
        for (int it = 0; it < 8; ++it) {
            int idx = tid + it * 256;          // 0..2047 float4s
            int m   = idx >> 4;
            int c4  = idx & 15;
            int oh  = oh0 + (m >> 5);
            int ow  = m & 31;
            int ih  = oh + kh;
            int iw  = ow + kw;
            float4 v = make_float4(0.f, 0.f, 0.f, 0.f);
            if ((unsigned)ih < HH && (unsigned)iw < WW)
                v = *(const float4*)(xb + (ih * WW + iw) * CC + c4 * 4);
            uint32_t h01 = bf2(v.y, v.x);
            uint32_t h23 = bf2(v.w, v.z);
            float r0 = v.x - __uint_as_float(h01 << 16);
            float r1 = v.y - __uint_as_float(h01 & 0xFFFF0000u);
            float r2 = v.z - __uint_as_float(h23 << 16);
            float r3 = v.w - __uint_as_float(h23 & 0xFFFF0000u);
            uint32_t l01 = bf2(r1, r0);
            uint32_t l23 = bf2(r3, r2);
            uint32_t off = m * 128 + ((c4 * 8) ^ ((m & 7) << 4));  // swizzled
            *(uint2*)(smem + A_HI + off) = make_uint2(h01, h23);
            *(uint2*)(smem + A_LO + off) = make_uint2(l01, l23);
        }
        // -- B tile: copy pre-split weights [128 f][64 c], swizzled ---------
        const char* kh_ = kh_base + (size_t)kp * (FF * CC * 2);
        const char* kl_ = kl_base + (size_t)kp * (FF * CC * 2);
        #pragma unroll
        for (int it = 0; it < 8; ++it) {
            int idx = tid + it * 256;          // 0..2047 uint4s (hi then lo)
            int t   = idx >> 10;
            int rem = idx & 1023;
            int f   = rem >> 3, u = rem & 7;
            const uint4* src = (const uint4*)((t ? kl_ : kh_) + f * 128 + u * 16);
            uint32_t dst = (t ? B_LO : B_HI) + f * 128 + ((u * 16) ^ ((f & 7) << 4));
            *(uint4*)(smem + dst) = *src;
        }
        __syncthreads();

        // -- 3 passes: hi*hi, lo*hi, hi*lo ----------------------------------
        #pragma unroll 1
        for (int pass = 0; pass < 3; ++pass) {
            const uint32_t Ab = sb + (pass == 1 ? A_LO : A_HI);
            const uint32_t Bb = sb + (pass == 2 ? B_LO : B_HI);
            #pragma unroll
            for (int ks = 0; ks < 4; ++ks) {
                uint32_t afr[4][4];
                #pragma unroll
                for (int mi = 0; mi < 4; mi++) {
                    int row = warp_m * 64 + mi * 16 + a_m;
                    uint32_t addr = Ab + row * 128 + ((ks * 32 + a_k) ^ ((row & 7) << 4));
                    ldsm4(afr[mi], addr);
                }
                uint32_t bfr[2][4];
                #pragma unroll
                for (int nj = 0; nj < 2; nj++) {
                    int row = warp_n * 32 + nj * 16 + b_n;
                    uint32_t addr = Bb + row * 128 + ((ks * 32 + b_k) ^ ((row & 7) << 4));
                    ldsm4(bfr[nj], addr);
                }
                #pragma unroll
                for (int mi = 0; mi < 4; mi++)
                    #pragma unroll
                    for (int ni = 0; ni < 4; ni++)
                        mma_bf16(acc[mi][ni], afr[mi],
                                 bfr[ni >> 1][(ni & 1) * 2],
                                 bfr[ni >> 1][(ni & 1) * 2 + 1]);
            }
        }
    }

    // ---- epilogue: direct f32 stores (float2 per ni frag) ------------------
    const size_t obase = (size_t)(b * I_ + img) * (HH * WW);
    #pragma unroll
    for (int mi = 0; mi < 4; mi++) {
        #pragma unroll
        for (int half = 0; half < 2; half++) {
            int m  = warp_m * 64 + mi * 16 + (lane >> 2) + half * 8;
            int oh = oh0 + (m >> 5);
            int ow = m & 31;
            float* op = out + (obase + oh * WW + ow) * FF + warp_n * 32 + (lane & 3) * 2;
            #pragma unroll
            for (int ni = 0; ni < 4; ni++) {
                float2 v = make_float2(acc[mi][ni][half * 2], acc[mi][ni][half * 2 + 1]);
                *(float2*)(op + ni * 8) = v;
            }
        }
    }
}

// ----------------------------------------------------------------- launch ---
extern "C" void kernel_launch(void* const* d_in, const int* in_sizes, int n_in,
                              void* d_out, int out_size)
{
    const float* x = (const float*)d_in[0];   // (8,16,32,32,64) f32
    const float* k = (const float*)d_in[1];   // (8,3,3,64,128)  f32
    float* out = (float*)d_out;               // (8,16,32,32,128) f32

    cudaFuncSetAttribute(conv_mma_kernel,
                         cudaFuncAttributeMaxDynamicSharedMemorySize, SMEM_TOTAL);

    wt_convert_kernel<<<72, 256>>>(k);
    dim3 grid(8, 16, 8);                      // (row-group, image, batch)
    conv_mma_kernel<<<grid, 256, SMEM_TOTAL>>>(x, out);
}

// round 11
// speedup vs baseline: 2.5350x; 1.0364x over previous
#include <cuda_runtime.h>
#include <cuda_bf16.h>
#include <cstdint>

#define B_ 8
#define I_ 16
#define HH 32
#define WW 32
#define CC 64
#define FF 128

// Pre-converted / transposed weights: [(b*9+kp)][f][c], bf16 hi + lo halves.
__device__ __align__(128) __nv_bfloat16 g_khi[72 * FF * CC];
__device__ __align__(128) __nv_bfloat16 g_klo[72 * FF * CC];

// ---- smem layout ------------------------------------------------------------
// Halo: 204 rows (6 ih x 34 iw) x 128B (64 bf16), hi + lo. B: [128 f][64 c].
#define HALO_HI 0
#define HALO_LO 26112
#define BB_HI   52224
#define BB_LO   68608
#define SMEM_TOTAL 84992

__device__ __forceinline__ uint32_t s2u(const void* p) {
    uint32_t a;
    asm("{ .reg .u64 t; cvta.to.shared.u64 t, %1; cvt.u32.u64 %0, t; }" : "=r"(a) : "l"(p));
    return a;
}
// pack bf16(hi_src)<<16 | bf16(lo_src)
__device__ __forceinline__ uint32_t bf2(float hi_src, float lo_src) {
    uint32_t r;
    asm("cvt.rn.bf16x2.f32 %0, %1, %2;" : "=r"(r) : "f"(hi_src), "f"(lo_src));
    return r;
}
__device__ __forceinline__ void ldsm4(uint32_t* r, uint32_t addr) {
    asm volatile("ldmatrix.sync.aligned.m8n8.x4.shared.b16 {%0,%1,%2,%3}, [%4];"
                 : "=r"(r[0]), "=r"(r[1]), "=r"(r[2]), "=r"(r[3]) : "r"(addr));
}
__device__ __forceinline__ void mma_bf16(float* d, const uint32_t* a, uint32_t b0, uint32_t b1) {
    asm volatile(
        "mma.sync.aligned.m16n8k16.row.col.f32.bf16.bf16.f32 "
        "{%0,%1,%2,%3}, {%4,%5,%6,%7}, {%8,%9}, {%0,%1,%2,%3};"
        : "+f"(d[0]), "+f"(d[1]), "+f"(d[2]), "+f"(d[3])
        : "r"(a[0]), "r"(a[1]), "r"(a[2]), "r"(a[3]), "r"(b0), "r"(b1));
}

// ------------------------------------------------ weight convert/transpose --
// kern[b][kh][kw][c][f] f32  ->  g_khi/g_klo[(b*9+kp)][f][c] bf16
__global__ void __launch_bounds__(256) wt_convert_kernel(const float* __restrict__ kern) {
    __shared__ unsigned short shi[FF * 66];   // pad 64->66 to kill bank conflicts
    __shared__ unsigned short slo[FF * 66];
    const int blk = blockIdx.x;               // b*9+kp, 72 blocks
    const float* in = kern + (size_t)blk * (CC * FF);

    for (int idx = threadIdx.x; idx < CC * FF; idx += 256) {
        int c = idx >> 7, f = idx & 127;      // in is [c][f], reads coalesced
        float v = in[idx];
        __nv_bfloat16 h = __float2bfloat16(v);
        float hf = __bfloat162float(h);
        __nv_bfloat16 l = __float2bfloat16(v - hf);
        shi[f * 66 + c] = __bfloat16_as_ushort(h);
        slo[f * 66 + c] = __bfloat16_as_ushort(l);
    }
    __syncthreads();
    unsigned short* oh = (unsigned short*)(g_khi + (size_t)blk * (FF * CC));
    unsigned short* ol = (unsigned short*)(g_klo + (size_t)blk * (FF * CC));
    for (int idx = threadIdx.x; idx < FF * CC; idx += 256) {
        int f = idx >> 6, c = idx & 63;
        oh[idx] = shi[f * 66 + c];
        ol[idx] = slo[f * 66 + c];
    }
}

// ---------------------------------------------------------- main MMA kernel -
// Tile: M=128 (4 oh rows x 32 ow) x N=128 filters, K = 9 kp x 64 c.
// x halo converted to bf16 hi/lo ONCE; per-kp A tiles are pure addressing
// into the halo. 3-term split: hi*hi + lo*hi + hi*lo.
// 8 warps: warp_m = wid&1, warp_n = wid>>1.
// B tile loaded via plain LDG+STS (proven R7 path).
__global__ void __launch_bounds__(256, 2)
conv_mma_kernel(const float* __restrict__ x, float* __restrict__ out)
{
    extern __shared__ char smem[];
    const uint32_t sb = s2u(smem);
    const int tid  = threadIdx.x;
    const int lane = tid & 31;
    const int wid  = tid >> 5;
    const int warp_m = wid & 1;
    const int warp_n = wid >> 1;

    const int oh0 = blockIdx.x * 4;
    const int img = blockIdx.y;
    const int b   = blockIdx.z;
    const float* xb = x + (size_t)(b * I_ + img) * (HH * WW * CC);
    const char* kh_base = (const char*)(g_khi + (size_t)(b * 9) * (FF * CC));
    const char* kl_base = (const char*)(g_klo + (size_t)(b * 9) * (FF * CC));

    // ---- Convert x halo once: rows r = ih_rel*34 + iw_rel, 204 rows --------
    for (int idx = tid; idx < 204 * 16; idx += 256) {
        int r  = idx >> 4;            // halo row
        int c4 = idx & 15;            // float4 index within 64 c
        int ih = oh0 - 1 + r / 34;
        int iw = r % 34 - 1;
        float4 v = make_float4(0.f, 0.f, 0.f, 0.f);
        if ((unsigned)ih < HH && (unsigned)iw < WW)
            v = *(const float4*)(xb + (ih * WW + iw) * CC + c4 * 4);
        uint32_t h01 = bf2(v.y, v.x);
        uint32_t h23 = bf2(v.w, v.z);
        float r0 = v.x - __uint_as_float(h01 << 16);
        float r1 = v.y - __uint_as_float(h01 & 0xFFFF0000u);
        float r2 = v.z - __uint_as_float(h23 << 16);
        float r3 = v.w - __uint_as_float(h23 & 0xFFFF0000u);
        uint32_t l01 = bf2(r1, r0);
        uint32_t l23 = bf2(r3, r2);
        uint32_t off = r * 128 + ((c4 * 8) ^ ((r & 7) << 4));   // swizzled
        *(uint2*)(smem + HALO_HI + off) = make_uint2(h01, h23);
        *(uint2*)(smem + HALO_LO + off) = make_uint2(l01, l23);
    }

    float acc[4][4][4];   // [mi][ni][reg]
    #pragma unroll
    for (int mi = 0; mi < 4; mi++)
        #pragma unroll
        for (int ni = 0; ni < 4; ni++)
            #pragma unroll
            for (int r = 0; r < 4; r++) acc[mi][ni][r] = 0.f;

    // per-lane ldmatrix address components
    const int a_m = lane & 15;                 // row within m16
    const int a_k = (lane >> 4) << 4;          // 0 / 16 byte (k half)
    const int b_n = (lane & 7) + ((lane >> 4) << 3);  // row within n16
    const int b_k = ((lane >> 3) & 1) << 4;    // 0 / 16 byte (k half)

    // halo row (minus rbase) for each mi
    int hrow[4];
    #pragma unroll
    for (int mi = 0; mi < 4; mi++) {
        int m = warp_m * 64 + mi * 16 + a_m;
        hrow[mi] = (m >> 5) * 34 + (m & 31);
    }
    // B ldsm row base + swizzle mask (XOR applied to FULL k-offset per ks)
    uint32_t brow[2], bmask[2];
    #pragma unroll
    for (int nj = 0; nj < 2; nj++) {
        int row = warp_n * 32 + nj * 16 + b_n;
        brow[nj]  = (uint32_t)row * 128;
        bmask[nj] = (uint32_t)((row & 7) << 4);
    }

    __syncthreads();   // halo ready

    #pragma unroll 1
    for (int kp = 0; kp < 9; ++kp) {
        const int rbase = (kp / 3) * 34 + (kp % 3);

        // -- B tile: plain LDG+STS [128 f][64 c] hi+lo, swizzled (R7 path) ---
        const char* kh_ = kh_base + (size_t)kp * (FF * CC * 2);
        const char* kl_ = kl_base + (size_t)kp * (FF * CC * 2);
        #pragma unroll
        for (int it = 0; it < 8; ++it) {
            int idx = tid + it * 256;          // 0..2047 uint4s (hi then lo)
            int t   = idx >> 10;
            int rem = idx & 1023;
            int f   = rem >> 3, u = rem & 7;
            const uint4* src = (const uint4*)((t ? kl_ : kh_) + f * 128 + u * 16);
            uint32_t dst = (t ? BB_LO : BB_HI) + f * 128 + ((u * 16) ^ ((f & 7) << 4));
            *(uint4*)(smem + dst) = *src;
        }
        __syncthreads();   // B visible to all warps

        // -- compute: 4 k16-steps; A direct from halo ------------------------
        #pragma unroll
        for (int ks = 0; ks < 4; ++ks) {
            uint32_t ah[4][4], al[4][4];
            #pragma unroll
            for (int mi = 0; mi < 4; mi++) {
                int r = rbase + hrow[mi];
                uint32_t ro = (uint32_t)r * 128 + ((ks * 32 + a_k) ^ ((r & 7) << 4));
                ldsm4(ah[mi], sb + HALO_HI + ro);
                ldsm4(al[mi], sb + HALO_LO + ro);
            }
            uint32_t bh[2][4];
            #pragma unroll
            for (int nj = 0; nj < 2; nj++)
                ldsm4(bh[nj], sb + BB_HI + brow[nj] + ((ks * 32 + b_k) ^ bmask[nj]));
            #pragma unroll
            for (int mi = 0; mi < 4; mi++)
                #pragma unroll
                for (int ni = 0; ni < 4; ni++)
                    mma_bf16(acc[mi][ni], ah[mi],
                             bh[ni >> 1][(ni & 1) * 2], bh[ni >> 1][(ni & 1) * 2 + 1]);
            #pragma unroll
            for (int mi = 0; mi < 4; mi++)
                #pragma unroll
                for (int ni = 0; ni < 4; ni++)
                    mma_bf16(acc[mi][ni], al[mi],
                             bh[ni >> 1][(ni & 1) * 2], bh[ni >> 1][(ni & 1) * 2 + 1]);
            uint32_t bl[2][4];
            #pragma unroll
            for (int nj = 0; nj < 2; nj++)
                ldsm4(bl[nj], sb + BB_LO + brow[nj] + ((ks * 32 + b_k) ^ bmask[nj]));
            #pragma unroll
            for (int mi = 0; mi < 4; mi++)
                #pragma unroll
                for (int ni = 0; ni < 4; ni++)
                    mma_bf16(acc[mi][ni], ah[mi],
                             bl[ni >> 1][(ni & 1) * 2], bl[ni >> 1][(ni & 1) * 2 + 1]);
        }
        __syncthreads();   // compute done before next kp overwrites B
    }

    // ---- epilogue: direct f32 stores (float2 per ni frag) ------------------
    const size_t obase = (size_t)(b * I_ + img) * (HH * WW);
    #pragma unroll
    for (int mi = 0; mi < 4; mi++) {
        #pragma unroll
        for (int half = 0; half < 2; half++) {
            int m  = warp_m * 64 + mi * 16 + (lane >> 2) + half * 8;
            int oh = oh0 + (m >> 5);
            int ow = m & 31;
            float* op = out + (obase + oh * WW + ow) * FF + warp_n * 32 + (lane & 3) * 2;
            #pragma unroll
            for (int ni = 0; ni < 4; ni++) {
                float2 v = make_float2(acc[mi][ni][half * 2], acc[mi][ni][half * 2 + 1]);
                *(float2*)(op + ni * 8) = v;
            }
        }
    }
}

// ----------------------------------------------------------------- launch ---
extern "C" void kernel_launch(void* const* d_in, const int* in_sizes, int n_in,
                              void* d_out, int out_size)
{
    const float* x = (const float*)d_in[0];   // (8,16,32,32,64) f32
    const float* k = (const float*)d_in[1];   // (8,3,3,64,128)  f32
    float* out = (float*)d_out;               // (8,16,32,32,128) f32

    cudaFuncSetAttribute(conv_mma_kernel,
                         cudaFuncAttributeMaxDynamicSharedMemorySize, SMEM_TOTAL);

    wt_convert_kernel<<<72, 256>>>(k);
    dim3 grid(8, 16, 8);                      // (row-group, image, batch)
    conv_mma_kernel<<<grid, 256, SMEM_TOTAL>>>(x, out);
}